// round 14
// baseline (speedup 1.0000x reference)
#include <cuda_runtime.h>
#include <cuda_fp16.h>
#include <math.h>

#define NQ     8192
#define NKV    2048
#define CDIM   512
#define HEADS  8
#define DH     64
#define FF     1024
#define LN_EPS 1e-5f

// ---------------- scratch (device globals) ----------------
__device__ __half g_qn[NQ * CDIM];
__device__ __half g_kn[NKV * CDIM];
__device__ __half g_vn[NKV * CDIM];
__device__ __half g_qh[NQ * CDIM];
__device__ __half g_kh[NKV * CDIM];
__device__ __half g_vh[NKV * CDIM];
__device__ __half g_at[NQ * CDIM];
__device__ __half g_z0[NQ * CDIM];
__device__ __half g_z1[NQ * CDIM];
__device__ __half g_h1[NQ * FF];
__device__ float  g_z2[NQ * CDIM];
__device__ __half g_Wqh[CDIM * CDIM];
__device__ __half g_Wkh[CDIM * CDIM];
__device__ __half g_Wvh[CDIM * CDIM];
__device__ __half g_Wph[CDIM * CDIM];
__device__ __half g_W1h[CDIM * FF];
__device__ __half g_W2h[FF * CDIM];

// ---------------- async copy helpers ----------------
__device__ __forceinline__ void cp16(void* sdst, const void* gsrc) {
    unsigned d = (unsigned)__cvta_generic_to_shared(sdst);
    asm volatile("cp.async.cg.shared.global [%0], [%1], 16;\n" :: "r"(d), "l"(gsrc));
}
__device__ __forceinline__ void cp_commit() {
    asm volatile("cp.async.commit_group;\n");
}
__device__ __forceinline__ void cp_wait1() {
    asm volatile("cp.async.wait_group 1;\n");
}
__device__ __forceinline__ void cp_wait0() {
    asm volatile("cp.async.wait_group 0;\n");
}

// ---------------- ldmatrix helpers ----------------
__device__ __forceinline__ void ldsm_x4(unsigned& r0, unsigned& r1, unsigned& r2,
                                        unsigned& r3, const __half* p) {
    unsigned a = (unsigned)__cvta_generic_to_shared(p);
    asm volatile("ldmatrix.sync.aligned.m8n8.x4.shared.b16 {%0,%1,%2,%3}, [%4];\n"
                 : "=r"(r0), "=r"(r1), "=r"(r2), "=r"(r3) : "r"(a));
}
__device__ __forceinline__ void ldsm_x4_t(unsigned& r0, unsigned& r1, unsigned& r2,
                                          unsigned& r3, const __half* p) {
    unsigned a = (unsigned)__cvta_generic_to_shared(p);
    asm volatile("ldmatrix.sync.aligned.m8n8.x4.trans.shared.b16 {%0,%1,%2,%3}, [%4];\n"
                 : "=r"(r0), "=r"(r1), "=r"(r2), "=r"(r3) : "r"(a));
}

// ---------------- mma.sync helper ----------------
__device__ __forceinline__ void mma16816(float* c, const unsigned* a, const unsigned* b) {
    asm volatile(
        "mma.sync.aligned.m16n8k16.row.col.f32.f16.f16.f32 "
        "{%0,%1,%2,%3}, {%4,%5,%6,%7}, {%8,%9}, {%0,%1,%2,%3};"
        : "+f"(c[0]), "+f"(c[1]), "+f"(c[2]), "+f"(c[3])
        : "r"(a[0]), "r"(a[1]), "r"(a[2]), "r"(a[3]), "r"(b[0]), "r"(b[1]));
}

// ---------------- all weight converts in one launch ----------------
__global__ void f2h_all(const float* Wq, const float* Wk, const float* Wv,
                        const float* Wp, const float* W1, const float* W2,
                        __half* Wqh, __half* Wkh, __half* Wvh,
                        __half* Wph, __half* W1h, __half* W2h) {
    int i = blockIdx.x * 256 + threadIdx.x;   // pair index
    const float* s; __half* d; int o;
    if      (i <  131072) { s = Wq; d = Wqh; o = i; }
    else if (i <  262144) { s = Wk; d = Wkh; o = i - 131072; }
    else if (i <  393216) { s = Wv; d = Wvh; o = i - 262144; }
    else if (i <  524288) { s = Wp; d = Wph; o = i - 393216; }
    else if (i <  786432) { s = W1; d = W1h; o = i - 524288; }
    else                  { s = W2; d = W2h; o = i - 786432; }
    float2 v = ((const float2*)s)[o];
    ((half2*)d)[o] = __floats2half2_rn(v.x, v.y);
}

// ---------------- batched channel-major LN: q/k/v in one launch ----------------
#define LDT 17
__global__ __launch_bounds__(256) void ln_in_all(
        const float* __restrict__ xq, const float* __restrict__ xk, const float* __restrict__ xv,
        const float* __restrict__ gq, const float* __restrict__ bq_,
        const float* __restrict__ gk, const float* __restrict__ bk_,
        const float* __restrict__ gv, const float* __restrict__ bv_,
        __half* __restrict__ yq, __half* __restrict__ yk, __half* __restrict__ yv) {
    __shared__ float t[512 * LDT];
    __shared__ float smu[16], srs[16];
    int bid = blockIdx.x, tid = threadIdx.x;
    const float *x, *g, *b; __half* y; int N, n0;
    if (bid < 512)      { x = xq; g = gq; b = bq_; y = yq; N = NQ;  n0 = bid * 16; }
    else if (bid < 640) { x = xk; g = gk; b = bk_; y = yk; N = NKV; n0 = (bid - 512) * 16; }
    else                { x = xv; g = gv; b = bv_; y = yv; N = NKV; n0 = (bid - 640) * 16; }
#pragma unroll
    for (int p = 0; p < 32; p++) {
        int ch = p * 16 + (tid >> 4), tok = tid & 15;
        t[ch * LDT + tok] = x[(size_t)ch * N + n0 + tok];
    }
    __syncthreads();
    int w = tid >> 5, lane = tid & 31;
    int tok = 2 * w + (lane >> 4), lid = lane & 15;
    float s = 0.f, s2 = 0.f;
#pragma unroll
    for (int i = 0; i < 32; i++) {
        float v = t[(lid + i * 16) * LDT + tok];
        s += v; s2 += v * v;
    }
#pragma unroll
    for (int o = 1; o < 16; o <<= 1) {
        s  += __shfl_xor_sync(0xffffffffu, s,  o);
        s2 += __shfl_xor_sync(0xffffffffu, s2, o);
    }
    if (lid == 0) {
        float m = s * (1.0f / CDIM);
        smu[tok] = m;
        srs[tok] = rsqrtf(s2 * (1.0f / CDIM) - m * m + LN_EPS);
    }
    __syncthreads();
#pragma unroll
    for (int p = 0; p < 16; p++) {
        int flat = p * 256 + tid;
        int tk = flat >> 8, ch = (flat & 255) * 2;
        float mu = smu[tk], rs = srs[tk];
        float v0 = (t[ch * LDT + tk] - mu) * rs * g[ch] + b[ch];
        float v1 = (t[(ch + 1) * LDT + tk] - mu) * rs * g[ch + 1] + b[ch + 1];
        ((half2*)(y + (size_t)(n0 + tk) * CDIM))[ch >> 1] = __floats2half2_rn(v0, v1);
    }
}

// ---------------- fused row LN + transpose out ----------------
#define LDZ 513
__global__ __launch_bounds__(256) void ln_out_fused(
        const float* __restrict__ z, const float* __restrict__ g,
        const float* __restrict__ b, float* __restrict__ out, int N) {
    __shared__ float t[16 * LDZ];
    __shared__ float smu[16], srs[16];
    int n0 = blockIdx.x * 16, tid = threadIdx.x;
#pragma unroll
    for (int p = 0; p < 8; p++) {
        int f4 = p * 256 + tid;
        int tok = f4 >> 7, ch = (f4 & 127) * 4;
        float4 v = ((const float4*)(z + (size_t)(n0 + tok) * CDIM))[f4 & 127];
        t[tok * LDZ + ch] = v.x; t[tok * LDZ + ch + 1] = v.y;
        t[tok * LDZ + ch + 2] = v.z; t[tok * LDZ + ch + 3] = v.w;
    }
    __syncthreads();
    int w = tid >> 5, lane = tid & 31;
    int tok = 2 * w + (lane >> 4), lid = lane & 15;
    float s = 0.f, s2 = 0.f;
#pragma unroll
    for (int i = 0; i < 32; i++) {
        float v = t[tok * LDZ + lid + i * 16];
        s += v; s2 += v * v;
    }
#pragma unroll
    for (int o = 1; o < 16; o <<= 1) {
        s  += __shfl_xor_sync(0xffffffffu, s,  o);
        s2 += __shfl_xor_sync(0xffffffffu, s2, o);
    }
    if (lid == 0) {
        float m = s * (1.0f / CDIM);
        smu[tok] = m;
        srs[tok] = rsqrtf(s2 * (1.0f / CDIM) - m * m + LN_EPS);
    }
    __syncthreads();
#pragma unroll
    for (int p = 0; p < 32; p++) {
        int flat = p * 256 + tid;
        int ch = flat >> 4, tk = flat & 15;
        out[(size_t)ch * N + n0 + tk] =
            (t[tk * LDZ + ch] - smu[tk]) * srs[tk] * g[ch] + b[ch];
    }
}

// ---------------- row LN fp16 -> fp16 ----------------
__global__ void ln_rows_h(const __half* __restrict__ x, const float* __restrict__ g,
                          const float* __restrict__ b, __half* __restrict__ y) {
    int row = blockIdx.x;
    int tid = threadIdx.x;
    const __half* xr = x + (size_t)row * CDIM;
    float v0 = __half2float(xr[tid]), v1 = __half2float(xr[tid + 256]);
    float s = v0 + v1, s2 = v0 * v0 + v1 * v1;
#pragma unroll
    for (int o = 16; o > 0; o >>= 1) {
        s  += __shfl_xor_sync(0xffffffffu, s,  o);
        s2 += __shfl_xor_sync(0xffffffffu, s2, o);
    }
    __shared__ float sw[8], sw2[8];
    if ((tid & 31) == 0) { sw[tid >> 5] = s; sw2[tid >> 5] = s2; }
    __syncthreads();
    float ts = 0.f, ts2 = 0.f;
#pragma unroll
    for (int i = 0; i < 8; i++) { ts += sw[i]; ts2 += sw2[i]; }
    float m = ts * (1.0f / CDIM);
    float rstd = rsqrtf(ts2 * (1.0f / CDIM) - m * m + LN_EPS);
    __half* yr = y + (size_t)row * CDIM;
    yr[tid]       = __float2half_rn((v0 - m) * rstd * g[tid]       + b[tid]);
    yr[tid + 256] = __float2half_rn((v1 - m) * rstd * g[tid + 256] + b[tid + 256]);
}

// ---------------- GEMM (R11 exact): raw mma, 128x128 tile, 8 warps x 32x64, BK=32,
//                  cp.async 3-stage, 1 sync/iter, direct-register epilogue ----------------
#define LDA_S 40
#define LDB_S 136
struct SmemGemm {
    __half As[3][128 * LDA_S];
    __half Bs[3][32 * LDB_S];
};

__device__ __forceinline__ void gemm_body(
        SmemGemm* sm,
        const __half* __restrict__ A, const __half* __restrict__ B,
        const float* __restrict__ bias, const __half* __restrict__ res,
        __half* __restrict__ Ch, float* __restrict__ Cf,
        int N, int K, int doGelu, int m0, int n0) {
    int tid = threadIdx.x;
    int lane = tid & 31;
    int w = tid >> 5;
    int wm = w >> 1, wn = w & 1;     // warp tile: rows 32*wm, cols 64*wn
    int tq = lane >> 2, tr = lane & 3;

    float acc[2][8][4];
#pragma unroll
    for (int i = 0; i < 2; i++)
#pragma unroll
        for (int j = 0; j < 8; j++)
#pragma unroll
            for (int r = 0; r < 4; r++) acc[i][j][r] = 0.f;

    int ar = tid >> 1, ac = (tid & 1) * 16;
    int br = tid >> 3, bc = (tid & 7) * 16;
    const __half* apb = A + (size_t)(m0 + ar) * K + ac;
    const __half* bpb = B + (size_t)br * N + n0 + bc;

    // prefetch tiles 0 and 1
#pragma unroll
    for (int p = 0; p < 2; p++) {
        int k0 = p * 32;
        cp16(&sm->As[p][ar * LDA_S + ac],     apb + k0);
        cp16(&sm->As[p][ar * LDA_S + ac + 8], apb + k0 + 8);
        cp16(&sm->Bs[p][br * LDB_S + bc],     bpb + (size_t)k0 * N);
        cp16(&sm->Bs[p][br * LDB_S + bc + 8], bpb + (size_t)k0 * N + 8);
        cp_commit();
    }

    const int ax_row = (lane & 15);
    const int ax_col = ((lane & 16) >> 1);
    const int bx_row = (lane & 15);
    const int bx_col = ((lane & 16) >> 1);

    int nT = K >> 5;
    int buf = 0;
    for (int t = 0; t < nT; t++) {
        if (t == nT - 1) cp_wait0(); else cp_wait1();
        __syncthreads();
        if (t + 2 < nT) {
            int k0 = (t + 2) * 32;
            int nb = (buf + 2 >= 3) ? buf - 1 : buf + 2;
            cp16(&sm->As[nb][ar * LDA_S + ac],     apb + k0);
            cp16(&sm->As[nb][ar * LDA_S + ac + 8], apb + k0 + 8);
            cp16(&sm->Bs[nb][br * LDB_S + bc],     bpb + (size_t)k0 * N);
            cp16(&sm->Bs[nb][br * LDB_S + bc + 8], bpb + (size_t)k0 * N + 8);
            cp_commit();
        }
        const __half* Asb = sm->As[buf];
        const __half* Bsb = sm->Bs[buf];
#pragma unroll
        for (int ks = 0; ks < 2; ks++) {
            unsigned af[2][4];
#pragma unroll
            for (int mi = 0; mi < 2; mi++)
                ldsm_x4(af[mi][0], af[mi][1], af[mi][2], af[mi][3],
                        &Asb[(32 * wm + 16 * mi + ax_row) * LDA_S + 16 * ks + ax_col]);
#pragma unroll
            for (int np = 0; np < 4; np++) {
                unsigned bb[4];
                ldsm_x4_t(bb[0], bb[1], bb[2], bb[3],
                          &Bsb[(16 * ks + bx_row) * LDB_S + 64 * wn + 16 * np + bx_col]);
#pragma unroll
                for (int mi = 0; mi < 2; mi++) {
                    mma16816(acc[mi][2 * np],     af[mi], bb);
                    mma16816(acc[mi][2 * np + 1], af[mi], bb + 2);
                }
            }
        }
        buf = (buf == 2) ? 0 : buf + 1;
    }

    // direct-register epilogue: rows tq / tq+8, cols 2*tr / 2*tr+1
#pragma unroll
    for (int mi = 0; mi < 2; mi++) {
        int r0 = m0 + 32 * wm + 16 * mi + tq;
        int r1 = r0 + 8;
#pragma unroll
        for (int nj = 0; nj < 8; nj++) {
            int col = n0 + 64 * wn + 8 * nj + 2 * tr;
            float b0 = bias[col], b1 = bias[col + 1];
            float v0 = acc[mi][nj][0] + b0;
            float v1 = acc[mi][nj][1] + b1;
            float v2 = acc[mi][nj][2] + b0;
            float v3 = acc[mi][nj][3] + b1;
            if (doGelu) {
                v0 = 0.5f * v0 * (1.0f + erff(v0 * 0.70710678118654752f));
                v1 = 0.5f * v1 * (1.0f + erff(v1 * 0.70710678118654752f));
                v2 = 0.5f * v2 * (1.0f + erff(v2 * 0.70710678118654752f));
                v3 = 0.5f * v3 * (1.0f + erff(v3 * 0.70710678118654752f));
            }
            if (res) {
                half2 r0v = *(const half2*)&res[(size_t)r0 * N + col];
                half2 r1v = *(const half2*)&res[(size_t)r1 * N + col];
                v0 += __half2float(r0v.x); v1 += __half2float(r0v.y);
                v2 += __half2float(r1v.x); v3 += __half2float(r1v.y);
            }
            if (Ch) {
                *(half2*)&Ch[(size_t)r0 * N + col] = __floats2half2_rn(v0, v1);
                *(half2*)&Ch[(size_t)r1 * N + col] = __floats2half2_rn(v2, v3);
            }
            if (Cf) {
                *(float2*)&Cf[(size_t)r0 * N + col] = make_float2(v0, v1);
                *(float2*)&Cf[(size_t)r1 * N + col] = make_float2(v2, v3);
            }
        }
    }
}

// generic GEMM (256 threads, 8 warps, 2 blocks/SM)
__global__ __launch_bounds__(256, 2) void hgemm(
        const __half* __restrict__ A, const __half* __restrict__ B,
        const float* __restrict__ bias, const __half* __restrict__ res,
        __half* __restrict__ Ch, float* __restrict__ Cf,
        int N, int K, int doGelu) {
    __shared__ SmemGemm sm;
    gemm_body(&sm, A, B, bias, res, Ch, Cf, N, K, doGelu,
              blockIdx.y * 128, blockIdx.x * 128);
}

// z-batched QKV projection
__global__ __launch_bounds__(256, 2) void qkv_gemm(
        const __half* qn, const __half* kn, const __half* vn,
        const __half* Wq, const __half* Wk, const __half* Wv,
        const float* bq, const float* bk, const float* bv,
        __half* qh, __half* kh, __half* vh) {
    const __half *A, *B; const float* bias; __half* C; int M;
    if (blockIdx.z == 0)      { A = qn; B = Wq; bias = bq; C = qh; M = NQ;  }
    else if (blockIdx.z == 1) { A = kn; B = Wk; bias = bk; C = kh; M = NKV; }
    else                      { A = vn; B = Wv; bias = bv; C = vh; M = NKV; }
    int m0 = blockIdx.y * 128;
    if (m0 >= M) return;
    __shared__ SmemGemm sm;
    gemm_body(&sm, A, B, bias, nullptr, C, nullptr, CDIM, CDIM, 0,
              m0, blockIdx.x * 128);
}

// ---------------- flash attention: 256 q x 1 head / block, 16 warps, BKV=64,
//                  3-stage KV ring, no-max h2exp2 softmax, 1 sync/iter ----------------
#define LDK 72
#define BQ  256
__global__ __launch_bounds__(512) void attn_h(
        const __half* __restrict__ qh, const __half* __restrict__ kh,
        const __half* __restrict__ vh, __half* __restrict__ outp) {
    __shared__ __half Qs[BQ * LDK];           // 36.9 KB, persistent
    __shared__ __half SM[3][2 * 64 * LDK];    // K then V per stage, 55.3 KB

    const int tid = threadIdx.x;
    const int lane = tid & 31;
    const int w = tid >> 5;            // 0..15, owns q rows 16w..16w+15
    const int h = blockIdx.y;
    const int q0 = blockIdx.x * BQ;
    const int tq = lane >> 2;
    const int tr = lane & 3;

    // KV loader mapping: 512 threads, 64x64 tile = 512 x16B chunks
    const int lrow = tid >> 3;              // 0..63
    const int lcol = (tid & 7) * 8;         // 0..56 (halfs)

    // loop-carried gmem prefetch pointers
    const __half* kgp = kh + (size_t)lrow * CDIM + h * DH + lcol;
    const __half* vgp = vh + (size_t)lrow * CDIM + h * DH + lcol;

    // prefetch KV tiles 0 and 1
#pragma unroll
    for (int p = 0; p < 2; p++) {
        cp16(&SM[p][lrow * LDK + lcol], kgp + (size_t)p * 64 * CDIM);
        cp16(&SM[p][64 * LDK + lrow * LDK + lcol], vgp + (size_t)p * 64 * CDIM);
        cp_commit();
    }
    kgp += (size_t)128 * CDIM;   // next prefetch target = tile 2
    vgp += (size_t)128 * CDIM;

    // ---- stage Q (256 x 64), scale folds 1/8 AND log2(e) for exp2 softmax ----
    {
        int r = tid >> 1, cb = (tid & 1) * 32;
        const __half* src = qh + (size_t)(q0 + r) * CDIM + h * DH + cb;
        half2 scale = __half2half2(__float2half(0.125f * 1.4426950408889634f));
        half2* d = (half2*)&Qs[r * LDK + cb];
#pragma unroll
        for (int i = 0; i < 16; i++)
            d[i] = __hmul2(((const half2*)src)[i], scale);
    }
    __syncthreads();   // Qs visible to all warps

    // Q fragments (registers, persistent)
    unsigned qa[4][4];
    {
        int r0 = 16 * w + tq, r1 = r0 + 8;
#pragma unroll
        for (int c = 0; c < 4; c++) {
            int d0 = c * 16 + 2 * tr;
            qa[c][0] = *(const unsigned*)&Qs[r0 * LDK + d0];
            qa[c][1] = *(const unsigned*)&Qs[r1 * LDK + d0];
            qa[c][2] = *(const unsigned*)&Qs[r0 * LDK + d0 + 8];
            qa[c][3] = *(const unsigned*)&Qs[r1 * LDK + d0 + 8];
        }
    }

    // x4 ldmatrix index helpers
    const int kx_row = (lane & 7) + ((lane & 16) >> 1);
    const int kx_col = (lane & 8);
    const int vx_row = (lane & 15);
    const int vx_col = ((lane & 16) >> 1);

    float l0 = 0.f, l1 = 0.f;     // per-lane partial sums (reduced at end)
    float oacc[8][4];
#pragma unroll
    for (int j = 0; j < 8; j++)
#pragma unroll
        for (int r = 0; r < 4; r++) oacc[j][r] = 0.f;

    const int NT = NKV / 64;   // 32
    int buf = 0;
    for (int it = 0; it < NT; it++) {
        if (it == NT - 1) cp_wait0(); else cp_wait1();
        __syncthreads();   // tile `it` ready for all; all warps done with tile it-1

        // prefetch tile it+2 into the ring slot freed by tile it-1
        if (it + 2 < NT) {
            int nb = (buf + 2 >= 3) ? buf - 1 : buf + 2;
            cp16(&SM[nb][lrow * LDK + lcol], kgp);
            cp16(&SM[nb][64 * LDK + lrow * LDK + lcol], vgp);
            cp_commit();
            kgp += (size_t)64 * CDIM;
            vgp += (size_t)64 * CDIM;
        }

        const __half* Kt = &SM[buf][0];
        const __half* Vt = &SM[buf][64 * LDK];

        // ---- S' = (Q*log2e/8) @ K^T ----
        float sacc[8][4];
#pragma unroll
        for (int j = 0; j < 8; j++)
#pragma unroll
            for (int r = 0; r < 4; r++) sacc[j][r] = 0.f;
#pragma unroll
        for (int jp = 0; jp < 4; jp++) {
#pragma unroll
            for (int c = 0; c < 4; c++) {
                unsigned bb[4];
                ldsm_x4(bb[0], bb[1], bb[2], bb[3],
                        &Kt[(jp * 16 + kx_row) * LDK + c * 16 + kx_col]);
                mma16816(sacc[2 * jp],     qa[c], bb);
                mma16816(sacc[2 * jp + 1], qa[c], bb + 2);
            }
        }

        // ---- softmax: fp16x2 exp2 (one MUFU per pair); result IS the P fragment ----
        unsigned pa[4][4];
#pragma unroll
        for (int j = 0; j < 8; j++) {
            half2 e0 = h2exp2(__floats2half2_rn(sacc[j][0], sacc[j][1]));
            half2 e1 = h2exp2(__floats2half2_rn(sacc[j][2], sacc[j][3]));
            float2 f0 = __half22float2(e0);
            float2 f1 = __half22float2(e1);
            l0 += f0.x + f0.y;
            l1 += f1.x + f1.y;
            pa[j >> 1][(j & 1) * 2 + 0] = *(unsigned*)&e0;
            pa[j >> 1][(j & 1) * 2 + 1] = *(unsigned*)&e1;
        }

        // ---- O += P @ V ----
#pragma unroll
        for (int jp = 0; jp < 4; jp++) {
#pragma unroll
            for (int c = 0; c < 4; c++) {
                unsigned bb[4];
                ldsm_x4_t(bb[0], bb[1], bb[2], bb[3],
                          &Vt[(c * 16 + vx_row) * LDK + jp * 16 + vx_col]);
                mma16816(oacc[2 * jp],     pa[c], bb);
                mma16816(oacc[2 * jp + 1], pa[c], bb + 2);
            }
        }
        buf = (buf == 2) ? 0 : buf + 1;
    }

    // ---- final row-sum reduction (deferred; sums are linear) ----
    l0 += __shfl_xor_sync(0xffffffffu, l0, 1);
    l0 += __shfl_xor_sync(0xffffffffu, l0, 2);
    l1 += __shfl_xor_sync(0xffffffffu, l1, 1);
    l1 += __shfl_xor_sync(0xffffffffu, l1, 2);

    // ---- normalize + write ----
    float inv0 = 1.0f / l0, inv1 = 1.0f / l1;
    int r0 = q0 + 16 * w + tq, r1 = r0 + 8;
#pragma unroll
    for (int j = 0; j < 8; j++) {
        int col = h * DH + j * 8 + 2 * tr;
        *(half2*)&outp[(size_t)r0 * CDIM + col] =
            __floats2half2_rn(oacc[j][0] * inv0, oacc[j][1] * inv0);
        *(half2*)&outp[(size_t)r1 * CDIM + col] =
            __floats2half2_rn(oacc[j][2] * inv1, oacc[j][3] * inv1);
    }
}

// ---------------- launch ----------------
extern "C" void kernel_launch(void* const* d_in, const int* in_sizes, int n_in,
                              void* d_out, int out_size) {
    const float* q        = (const float*)d_in[0];
    const float* k        = (const float*)d_in[1];
    const float* v        = (const float*)d_in[2];
    const float* ln_q_g   = (const float*)d_in[3];
    const float* ln_q_b   = (const float*)d_in[4];
    const float* ln_k_g   = (const float*)d_in[5];
    const float* ln_k_b   = (const float*)d_in[6];
    const float* ln_v_g   = (const float*)d_in[7];
    const float* ln_v_b   = (const float*)d_in[8];
    const float* Wq       = (const float*)d_in[9];
    const float* bq       = (const float*)d_in[10];
    const float* Wk       = (const float*)d_in[11];
    const float* bk       = (const float*)d_in[12];
    const float* Wv       = (const float*)d_in[13];
    const float* bv       = (const float*)d_in[14];
    const float* Wp       = (const float*)d_in[15];
    const float* bp       = (const float*)d_in[16];
    const float* ln_pre_g = (const float*)d_in[17];
    const float* ln_pre_b = (const float*)d_in[18];
    const float* W1       = (const float*)d_in[19];
    const float* b1       = (const float*)d_in[20];
    const float* W2       = (const float*)d_in[21];
    const float* b2       = (const float*)d_in[22];
    const float* ln_po_g  = (const float*)d_in[23];
    const float* ln_po_b  = (const float*)d_in[24];
    float* out = (float*)d_out;

    __half *qn, *kn, *vn, *qh, *kh, *vh, *at, *z0, *z1, *h1;
    __half *Wqh, *Wkh, *Wvh, *Wph, *W1h, *W2h;
    float *z2;
    cudaGetSymbolAddress((void**)&qn, g_qn);
    cudaGetSymbolAddress((void**)&kn, g_kn);
    cudaGetSymbolAddress((void**)&vn, g_vn);
    cudaGetSymbolAddress((void**)&qh, g_qh);
    cudaGetSymbolAddress((void**)&kh, g_kh);
    cudaGetSymbolAddress((void**)&vh, g_vh);
    cudaGetSymbolAddress((void**)&at, g_at);
    cudaGetSymbolAddress((void**)&z0, g_z0);
    cudaGetSymbolAddress((void**)&z1, g_z1);
    cudaGetSymbolAddress((void**)&h1, g_h1);
    cudaGetSymbolAddress((void**)&z2, g_z2);
    cudaGetSymbolAddress((void**)&Wqh, g_Wqh);
    cudaGetSymbolAddress((void**)&Wkh, g_Wkh);
    cudaGetSymbolAddress((void**)&Wvh, g_Wvh);
    cudaGetSymbolAddress((void**)&Wph, g_Wph);
    cudaGetSymbolAddress((void**)&W1h, g_W1h);
    cudaGetSymbolAddress((void**)&W2h, g_W2h);

    // 0) all weights -> fp16 (one launch)
    f2h_all<<<4096, 256>>>(Wq, Wk, Wv, Wp, W1, W2, Wqh, Wkh, Wvh, Wph, W1h, W2h);

    // 1) all three input LNs in one launch (range-batched)
    ln_in_all<<<768, 256>>>(q, k, v, ln_q_g, ln_q_b, ln_k_g, ln_k_b, ln_v_g, ln_v_b,
                            qn, kn, vn);

    // 2) QKV projections in one z-batched launch
    qkv_gemm<<<dim3(CDIM / 128, NQ / 128, 3), 256>>>(
        qn, kn, vn, Wqh, Wkh, Wvh, bq, bk, bv, qh, kh, vh);

    // 3) flash attention (16 warps, BKV=64, h2exp2 softmax)
    attn_h<<<dim3(NQ / BQ, HEADS), 512>>>(qh, kh, vh, at);

    // 4) output projection + pre-LN
    hgemm<<<dim3(CDIM / 128, NQ / 128), 256>>>(at, Wph, bp, nullptr, z0, nullptr, CDIM, CDIM, 0);
    ln_rows_h<<<NQ, 256>>>(z0, ln_pre_g, ln_pre_b, z1);

    // 5) MLP
    hgemm<<<dim3(FF / 128, NQ / 128), 256>>>(z1, W1h, b1, nullptr, h1, nullptr, FF, CDIM, 1);
    hgemm<<<dim3(CDIM / 128, NQ / 128), 256>>>(h1, W2h, b2, z1, nullptr, z2, CDIM, FF, 0);

    // 6) post-LN + transpose back to (C, N)
    ln_out_fused<<<NQ / 16, 256>>>(z2, ln_po_g, ln_po_b, out, NQ);
}

// round 15
// speedup vs baseline: 1.0246x; 1.0246x over previous
#include <cuda_runtime.h>
#include <cuda_fp16.h>
#include <math.h>

#define NQ     8192
#define NKV    2048
#define CDIM   512
#define HEADS  8
#define DH     64
#define FF     1024
#define LN_EPS 1e-5f

// ---------------- scratch (device globals) ----------------
__device__ __half g_qn[NQ * CDIM];
__device__ __half g_kn[NKV * CDIM];
__device__ __half g_vn[NKV * CDIM];
__device__ __half g_qh[NQ * CDIM];
__device__ __half g_kh[NKV * CDIM];
__device__ __half g_vh[NKV * CDIM];
__device__ __half g_at[NQ * CDIM];
__device__ __half g_z0[NQ * CDIM];
__device__ __half g_z1[NQ * CDIM];
__device__ __half g_h1[NQ * FF];
__device__ float  g_z2[NQ * CDIM];
__device__ __half g_Wqh[CDIM * CDIM];
__device__ __half g_Wkh[CDIM * CDIM];
__device__ __half g_Wvh[CDIM * CDIM];
__device__ __half g_Wph[CDIM * CDIM];
__device__ __half g_W1h[CDIM * FF];
__device__ __half g_W2h[FF * CDIM];

// ---------------- async copy helpers ----------------
__device__ __forceinline__ void cp16(void* sdst, const void* gsrc) {
    unsigned d = (unsigned)__cvta_generic_to_shared(sdst);
    asm volatile("cp.async.cg.shared.global [%0], [%1], 16;\n" :: "r"(d), "l"(gsrc));
}
__device__ __forceinline__ void cp_commit() {
    asm volatile("cp.async.commit_group;\n");
}
__device__ __forceinline__ void cp_wait2() {
    asm volatile("cp.async.wait_group 2;\n");
}
__device__ __forceinline__ void cp_wait1() {
    asm volatile("cp.async.wait_group 1;\n");
}
__device__ __forceinline__ void cp_wait0() {
    asm volatile("cp.async.wait_group 0;\n");
}

// ---------------- ldmatrix helpers ----------------
__device__ __forceinline__ void ldsm_x4(unsigned& r0, unsigned& r1, unsigned& r2,
                                        unsigned& r3, const __half* p) {
    unsigned a = (unsigned)__cvta_generic_to_shared(p);
    asm volatile("ldmatrix.sync.aligned.m8n8.x4.shared.b16 {%0,%1,%2,%3}, [%4];\n"
                 : "=r"(r0), "=r"(r1), "=r"(r2), "=r"(r3) : "r"(a));
}
__device__ __forceinline__ void ldsm_x4_t(unsigned& r0, unsigned& r1, unsigned& r2,
                                          unsigned& r3, const __half* p) {
    unsigned a = (unsigned)__cvta_generic_to_shared(p);
    asm volatile("ldmatrix.sync.aligned.m8n8.x4.trans.shared.b16 {%0,%1,%2,%3}, [%4];\n"
                 : "=r"(r0), "=r"(r1), "=r"(r2), "=r"(r3) : "r"(a));
}

// ---------------- mma.sync helper ----------------
__device__ __forceinline__ void mma16816(float* c, const unsigned* a, const unsigned* b) {
    asm volatile(
        "mma.sync.aligned.m16n8k16.row.col.f32.f16.f16.f32 "
        "{%0,%1,%2,%3}, {%4,%5,%6,%7}, {%8,%9}, {%0,%1,%2,%3};"
        : "+f"(c[0]), "+f"(c[1]), "+f"(c[2]), "+f"(c[3])
        : "r"(a[0]), "r"(a[1]), "r"(a[2]), "r"(a[3]), "r"(b[0]), "r"(b[1]));
}

// ---------------- all weight converts in one launch ----------------
__global__ void f2h_all(const float* Wq, const float* Wk, const float* Wv,
                        const float* Wp, const float* W1, const float* W2,
                        __half* Wqh, __half* Wkh, __half* Wvh,
                        __half* Wph, __half* W1h, __half* W2h) {
    int i = blockIdx.x * 256 + threadIdx.x;   // pair index
    const float* s; __half* d; int o;
    if      (i <  131072) { s = Wq; d = Wqh; o = i; }
    else if (i <  262144) { s = Wk; d = Wkh; o = i - 131072; }
    else if (i <  393216) { s = Wv; d = Wvh; o = i - 262144; }
    else if (i <  524288) { s = Wp; d = Wph; o = i - 393216; }
    else if (i <  786432) { s = W1; d = W1h; o = i - 524288; }
    else                  { s = W2; d = W2h; o = i - 786432; }
    float2 v = ((const float2*)s)[o];
    ((half2*)d)[o] = __floats2half2_rn(v.x, v.y);
}

// ---------------- batched channel-major LN: q/k/v in one launch ----------------
#define LDT 17
__global__ __launch_bounds__(256) void ln_in_all(
        const float* __restrict__ xq, const float* __restrict__ xk, const float* __restrict__ xv,
        const float* __restrict__ gq, const float* __restrict__ bq_,
        const float* __restrict__ gk, const float* __restrict__ bk_,
        const float* __restrict__ gv, const float* __restrict__ bv_,
        __half* __restrict__ yq, __half* __restrict__ yk, __half* __restrict__ yv) {
    __shared__ float t[512 * LDT];
    __shared__ float smu[16], srs[16];
    int bid = blockIdx.x, tid = threadIdx.x;
    const float *x, *g, *b; __half* y; int N, n0;
    if (bid < 512)      { x = xq; g = gq; b = bq_; y = yq; N = NQ;  n0 = bid * 16; }
    else if (bid < 640) { x = xk; g = gk; b = bk_; y = yk; N = NKV; n0 = (bid - 512) * 16; }
    else                { x = xv; g = gv; b = bv_; y = yv; N = NKV; n0 = (bid - 640) * 16; }
#pragma unroll
    for (int p = 0; p < 32; p++) {
        int ch = p * 16 + (tid >> 4), tok = tid & 15;
        t[ch * LDT + tok] = x[(size_t)ch * N + n0 + tok];
    }
    __syncthreads();
    int w = tid >> 5, lane = tid & 31;
    int tok = 2 * w + (lane >> 4), lid = lane & 15;
    float s = 0.f, s2 = 0.f;
#pragma unroll
    for (int i = 0; i < 32; i++) {
        float v = t[(lid + i * 16) * LDT + tok];
        s += v; s2 += v * v;
    }
#pragma unroll
    for (int o = 1; o < 16; o <<= 1) {
        s  += __shfl_xor_sync(0xffffffffu, s,  o);
        s2 += __shfl_xor_sync(0xffffffffu, s2, o);
    }
    if (lid == 0) {
        float m = s * (1.0f / CDIM);
        smu[tok] = m;
        srs[tok] = rsqrtf(s2 * (1.0f / CDIM) - m * m + LN_EPS);
    }
    __syncthreads();
#pragma unroll
    for (int p = 0; p < 16; p++) {
        int flat = p * 256 + tid;
        int tk = flat >> 8, ch = (flat & 255) * 2;
        float mu = smu[tk], rs = srs[tk];
        float v0 = (t[ch * LDT + tk] - mu) * rs * g[ch] + b[ch];
        float v1 = (t[(ch + 1) * LDT + tk] - mu) * rs * g[ch + 1] + b[ch + 1];
        ((half2*)(y + (size_t)(n0 + tk) * CDIM))[ch >> 1] = __floats2half2_rn(v0, v1);
    }
}

// ---------------- fused row LN + transpose out ----------------
#define LDZ 513
__global__ __launch_bounds__(256) void ln_out_fused(
        const float* __restrict__ z, const float* __restrict__ g,
        const float* __restrict__ b, float* __restrict__ out, int N) {
    __shared__ float t[16 * LDZ];
    __shared__ float smu[16], srs[16];
    int n0 = blockIdx.x * 16, tid = threadIdx.x;
#pragma unroll
    for (int p = 0; p < 8; p++) {
        int f4 = p * 256 + tid;
        int tok = f4 >> 7, ch = (f4 & 127) * 4;
        float4 v = ((const float4*)(z + (size_t)(n0 + tok) * CDIM))[f4 & 127];
        t[tok * LDZ + ch] = v.x; t[tok * LDZ + ch + 1] = v.y;
        t[tok * LDZ + ch + 2] = v.z; t[tok * LDZ + ch + 3] = v.w;
    }
    __syncthreads();
    int w = tid >> 5, lane = tid & 31;
    int tok = 2 * w + (lane >> 4), lid = lane & 15;
    float s = 0.f, s2 = 0.f;
#pragma unroll
    for (int i = 0; i < 32; i++) {
        float v = t[tok * LDZ + lid + i * 16];
        s += v; s2 += v * v;
    }
#pragma unroll
    for (int o = 1; o < 16; o <<= 1) {
        s  += __shfl_xor_sync(0xffffffffu, s,  o);
        s2 += __shfl_xor_sync(0xffffffffu, s2, o);
    }
    if (lid == 0) {
        float m = s * (1.0f / CDIM);
        smu[tok] = m;
        srs[tok] = rsqrtf(s2 * (1.0f / CDIM) - m * m + LN_EPS);
    }
    __syncthreads();
#pragma unroll
    for (int p = 0; p < 32; p++) {
        int flat = p * 256 + tid;
        int ch = flat >> 4, tk = flat & 15;
        out[(size_t)ch * N + n0 + tk] =
            (t[tk * LDZ + ch] - smu[tk]) * srs[tk] * g[ch] + b[ch];
    }
}

// ---------------- row LN fp16 -> fp16 (half2 vectorized) ----------------
__global__ void ln_rows_h(const __half* __restrict__ x, const float* __restrict__ g,
                          const float* __restrict__ b, __half* __restrict__ y) {
    int row = blockIdx.x;
    int tid = threadIdx.x;                 // 256 threads x half2 = 512 cols
    const half2* xr = (const half2*)(x + (size_t)row * CDIM);
    half2 hv = xr[tid];
    float v0 = __half2float(hv.x), v1 = __half2float(hv.y);
    float s = v0 + v1, s2 = v0 * v0 + v1 * v1;
#pragma unroll
    for (int o = 16; o > 0; o >>= 1) {
        s  += __shfl_xor_sync(0xffffffffu, s,  o);
        s2 += __shfl_xor_sync(0xffffffffu, s2, o);
    }
    __shared__ float sw[8], sw2[8];
    if ((tid & 31) == 0) { sw[tid >> 5] = s; sw2[tid >> 5] = s2; }
    __syncthreads();
    float ts = 0.f, ts2 = 0.f;
#pragma unroll
    for (int i = 0; i < 8; i++) { ts += sw[i]; ts2 += sw2[i]; }
    float m = ts * (1.0f / CDIM);
    float rstd = rsqrtf(ts2 * (1.0f / CDIM) - m * m + LN_EPS);
    float2 gv = ((const float2*)g)[tid];
    float2 bv = ((const float2*)b)[tid];
    half2* yr = (half2*)(y + (size_t)row * CDIM);
    yr[tid] = __floats2half2_rn((v0 - m) * rstd * gv.x + bv.x,
                                (v1 - m) * rstd * gv.y + bv.y);
}

// ---------------- GEMM: raw mma, 128x128 tile, 8 warps x 32x64, BK=32,
//                  cp.async 4-stage ring, 1 sync/iter, direct-register epilogue ----------------
#define LDA_S 40
#define LDB_S 136
struct SmemGemm {
    __half As[4][128 * LDA_S];
    __half Bs[4][32 * LDB_S];
};

__device__ __forceinline__ void gemm_body(
        SmemGemm* sm,
        const __half* __restrict__ A, const __half* __restrict__ B,
        const float* __restrict__ bias, const __half* __restrict__ res,
        __half* __restrict__ Ch, float* __restrict__ Cf,
        int N, int K, int doGelu, int m0, int n0) {
    int tid = threadIdx.x;
    int lane = tid & 31;
    int w = tid >> 5;
    int wm = w >> 1, wn = w & 1;     // warp tile: rows 32*wm, cols 64*wn
    int tq = lane >> 2, tr = lane & 3;

    float acc[2][8][4];
#pragma unroll
    for (int i = 0; i < 2; i++)
#pragma unroll
        for (int j = 0; j < 8; j++)
#pragma unroll
            for (int r = 0; r < 4; r++) acc[i][j][r] = 0.f;

    int ar = tid >> 1, ac = (tid & 1) * 16;
    int br = tid >> 3, bc = (tid & 7) * 16;
    const __half* apb = A + (size_t)(m0 + ar) * K + ac;
    const __half* bpb = B + (size_t)br * N + n0 + bc;

    // prefetch tiles 0, 1, 2
#pragma unroll
    for (int p = 0; p < 3; p++) {
        int k0 = p * 32;
        cp16(&sm->As[p][ar * LDA_S + ac],     apb + k0);
        cp16(&sm->As[p][ar * LDA_S + ac + 8], apb + k0 + 8);
        cp16(&sm->Bs[p][br * LDB_S + bc],     bpb + (size_t)k0 * N);
        cp16(&sm->Bs[p][br * LDB_S + bc + 8], bpb + (size_t)k0 * N + 8);
        cp_commit();
    }

    const int ax_row = (lane & 15);
    const int ax_col = ((lane & 16) >> 1);
    const int bx_row = (lane & 15);
    const int bx_col = ((lane & 16) >> 1);

    int nT = K >> 5;
    int buf = 0;
    for (int t = 0; t < nT; t++) {
        int rem = nT - 1 - t;                 // groups pending after tile t's
        if (rem >= 2) cp_wait2();
        else if (rem == 1) cp_wait1();
        else cp_wait0();
        __syncthreads();
        if (t + 3 < nT) {
            int k0 = (t + 3) * 32;
            int nb = (buf + 3) & 3;
            cp16(&sm->As[nb][ar * LDA_S + ac],     apb + k0);
            cp16(&sm->As[nb][ar * LDA_S + ac + 8], apb + k0 + 8);
            cp16(&sm->Bs[nb][br * LDB_S + bc],     bpb + (size_t)k0 * N);
            cp16(&sm->Bs[nb][br * LDB_S + bc + 8], bpb + (size_t)k0 * N + 8);
            cp_commit();
        }
        const __half* Asb = sm->As[buf];
        const __half* Bsb = sm->Bs[buf];
#pragma unroll
        for (int ks = 0; ks < 2; ks++) {
            unsigned af[2][4];
#pragma unroll
            for (int mi = 0; mi < 2; mi++)
                ldsm_x4(af[mi][0], af[mi][1], af[mi][2], af[mi][3],
                        &Asb[(32 * wm + 16 * mi + ax_row) * LDA_S + 16 * ks + ax_col]);
#pragma unroll
            for (int np = 0; np < 4; np++) {
                unsigned bb[4];
                ldsm_x4_t(bb[0], bb[1], bb[2], bb[3],
                          &Bsb[(16 * ks + bx_row) * LDB_S + 64 * wn + 16 * np + bx_col]);
#pragma unroll
                for (int mi = 0; mi < 2; mi++) {
                    mma16816(acc[mi][2 * np],     af[mi], bb);
                    mma16816(acc[mi][2 * np + 1], af[mi], bb + 2);
                }
            }
        }
        buf = (buf + 1) & 3;
    }

    // direct-register epilogue: rows tq / tq+8, cols 2*tr / 2*tr+1
#pragma unroll
    for (int mi = 0; mi < 2; mi++) {
        int r0 = m0 + 32 * wm + 16 * mi + tq;
        int r1 = r0 + 8;
#pragma unroll
        for (int nj = 0; nj < 8; nj++) {
            int col = n0 + 64 * wn + 8 * nj + 2 * tr;
            float b0 = bias[col], b1 = bias[col + 1];
            float v0 = acc[mi][nj][0] + b0;
            float v1 = acc[mi][nj][1] + b1;
            float v2 = acc[mi][nj][2] + b0;
            float v3 = acc[mi][nj][3] + b1;
            if (doGelu) {
                v0 = 0.5f * v0 * (1.0f + erff(v0 * 0.70710678118654752f));
                v1 = 0.5f * v1 * (1.0f + erff(v1 * 0.70710678118654752f));
                v2 = 0.5f * v2 * (1.0f + erff(v2 * 0.70710678118654752f));
                v3 = 0.5f * v3 * (1.0f + erff(v3 * 0.70710678118654752f));
            }
            if (res) {
                half2 r0v = *(const half2*)&res[(size_t)r0 * N + col];
                half2 r1v = *(const half2*)&res[(size_t)r1 * N + col];
                v0 += __half2float(r0v.x); v1 += __half2float(r0v.y);
                v2 += __half2float(r1v.x); v3 += __half2float(r1v.y);
            }
            if (Ch) {
                *(half2*)&Ch[(size_t)r0 * N + col] = __floats2half2_rn(v0, v1);
                *(half2*)&Ch[(size_t)r1 * N + col] = __floats2half2_rn(v2, v3);
            }
            if (Cf) {
                *(float2*)&Cf[(size_t)r0 * N + col] = make_float2(v0, v1);
                *(float2*)&Cf[(size_t)r1 * N + col] = make_float2(v2, v3);
            }
        }
    }
}

// generic GEMM (256 threads, 8 warps, 2 blocks/SM)
__global__ __launch_bounds__(256, 2) void hgemm(
        const __half* __restrict__ A, const __half* __restrict__ B,
        const float* __restrict__ bias, const __half* __restrict__ res,
        __half* __restrict__ Ch, float* __restrict__ Cf,
        int N, int K, int doGelu) {
    __shared__ SmemGemm sm;
    gemm_body(&sm, A, B, bias, res, Ch, Cf, N, K, doGelu,
              blockIdx.y * 128, blockIdx.x * 128);
}

// packed 1-D QKV projection: 256 Q-blocks + 64 K-blocks + 64 V-blocks = 384
__global__ __launch_bounds__(256, 2) void qkv_gemm(
        const __half* qn, const __half* kn, const __half* vn,
        const __half* Wq, const __half* Wk, const __half* Wv,
        const float* bq, const float* bk, const float* bv,
        __half* qh, __half* kh, __half* vh) {
    int bid = blockIdx.x;
    const __half *A, *B; const float* bias; __half* C; int sub;
    if (bid < 256)      { A = qn; B = Wq; bias = bq; C = qh; sub = bid; }
    else if (bid < 320) { A = kn; B = Wk; bias = bk; C = kh; sub = bid - 256; }
    else                { A = vn; B = Wv; bias = bv; C = vh; sub = bid - 320; }
    int m0 = (sub >> 2) * 128;
    int n0 = (sub & 3) * 128;
    __shared__ SmemGemm sm;
    gemm_body(&sm, A, B, bias, nullptr, C, nullptr, CDIM, CDIM, 0, m0, n0);
}

// ---------------- flash attention: 256 q x 1 head / block, 16 warps, BKV=64,
//                  3-stage KV ring, no-max exp2 softmax (fp32), 1 sync/iter ----------------
#define LDK 72
#define BQ  256
__global__ __launch_bounds__(512) void attn_h(
        const __half* __restrict__ qh, const __half* __restrict__ kh,
        const __half* __restrict__ vh, __half* __restrict__ outp) {
    __shared__ __half Qs[BQ * LDK];           // 36.9 KB, persistent
    __shared__ __half SM[3][2 * 64 * LDK];    // K then V per stage, 55.3 KB

    const int tid = threadIdx.x;
    const int lane = tid & 31;
    const int w = tid >> 5;            // 0..15, owns q rows 16w..16w+15
    const int h = blockIdx.y;
    const int q0 = blockIdx.x * BQ;
    const int tq = lane >> 2;
    const int tr = lane & 3;

    // KV loader mapping: 512 threads, 64x64 tile = 512 x16B chunks
    const int lrow = tid >> 3;              // 0..63
    const int lcol = (tid & 7) * 8;         // 0..56 (halfs)

    // loop-carried gmem prefetch pointers
    const __half* kgp = kh + (size_t)lrow * CDIM + h * DH + lcol;
    const __half* vgp = vh + (size_t)lrow * CDIM + h * DH + lcol;

    // prefetch KV tiles 0 and 1
#pragma unroll
    for (int p = 0; p < 2; p++) {
        cp16(&SM[p][lrow * LDK + lcol], kgp + (size_t)p * 64 * CDIM);
        cp16(&SM[p][64 * LDK + lrow * LDK + lcol], vgp + (size_t)p * 64 * CDIM);
        cp_commit();
    }
    kgp += (size_t)128 * CDIM;   // next prefetch target = tile 2
    vgp += (size_t)128 * CDIM;

    // ---- stage Q (256 x 64), scale folds 1/8 AND log2(e) for exp2 softmax ----
    {
        int r = tid >> 1, cb = (tid & 1) * 32;
        const __half* src = qh + (size_t)(q0 + r) * CDIM + h * DH + cb;
        half2 scale = __half2half2(__float2half(0.125f * 1.4426950408889634f));
        half2* d = (half2*)&Qs[r * LDK + cb];
#pragma unroll
        for (int i = 0; i < 16; i++)
            d[i] = __hmul2(((const half2*)src)[i], scale);
    }
    __syncthreads();   // Qs visible to all warps

    // Q fragments (registers, persistent)
    unsigned qa[4][4];
    {
        int r0 = 16 * w + tq, r1 = r0 + 8;
#pragma unroll
        for (int c = 0; c < 4; c++) {
            int d0 = c * 16 + 2 * tr;
            qa[c][0] = *(const unsigned*)&Qs[r0 * LDK + d0];
            qa[c][1] = *(const unsigned*)&Qs[r1 * LDK + d0];
            qa[c][2] = *(const unsigned*)&Qs[r0 * LDK + d0 + 8];
            qa[c][3] = *(const unsigned*)&Qs[r1 * LDK + d0 + 8];
        }
    }

    // x4 ldmatrix index helpers
    const int kx_row = (lane & 7) + ((lane & 16) >> 1);
    const int kx_col = (lane & 8);
    const int vx_row = (lane & 15);
    const int vx_col = ((lane & 16) >> 1);

    float l0 = 0.f, l1 = 0.f;     // per-lane partial sums (reduced at end)
    float oacc[8][4];
#pragma unroll
    for (int j = 0; j < 8; j++)
#pragma unroll
        for (int r = 0; r < 4; r++) oacc[j][r] = 0.f;

    const int NT = NKV / 64;   // 32
    int buf = 0;
    for (int it = 0; it < NT; it++) {
        if (it == NT - 1) cp_wait0(); else cp_wait1();
        __syncthreads();   // tile `it` ready for all; all warps done with tile it-1

        // prefetch tile it+2 into the ring slot freed by tile it-1
        if (it + 2 < NT) {
            int nb = (buf + 2 >= 3) ? buf - 1 : buf + 2;
            cp16(&SM[nb][lrow * LDK + lcol], kgp);
            cp16(&SM[nb][64 * LDK + lrow * LDK + lcol], vgp);
            cp_commit();
            kgp += (size_t)64 * CDIM;
            vgp += (size_t)64 * CDIM;
        }

        const __half* Kt = &SM[buf][0];
        const __half* Vt = &SM[buf][64 * LDK];

        // ---- S' = (Q*log2e/8) @ K^T ----
        float sacc[8][4];
#pragma unroll
        for (int j = 0; j < 8; j++)
#pragma unroll
            for (int r = 0; r < 4; r++) sacc[j][r] = 0.f;
#pragma unroll
        for (int jp = 0; jp < 4; jp++) {
#pragma unroll
            for (int c = 0; c < 4; c++) {
                unsigned bb[4];
                ldsm_x4(bb[0], bb[1], bb[2], bb[3],
                        &Kt[(jp * 16 + kx_row) * LDK + c * 16 + kx_col]);
                mma16816(sacc[2 * jp],     qa[c], bb);
                mma16816(sacc[2 * jp + 1], qa[c], bb + 2);
            }
        }

        // ---- softmax: fp32 exp2 (log2e folded into Q scale), no max subtraction ----
#pragma unroll
        for (int j = 0; j < 8; j++) {
            sacc[j][0] = exp2f(sacc[j][0]);
            sacc[j][1] = exp2f(sacc[j][1]);
            sacc[j][2] = exp2f(sacc[j][2]);
            sacc[j][3] = exp2f(sacc[j][3]);
            l0 += sacc[j][0] + sacc[j][1];
            l1 += sacc[j][2] + sacc[j][3];
        }

        // ---- P fragments from S accumulators (register-only) ----
        unsigned pa[4][4];
#pragma unroll
        for (int c = 0; c < 4; c++) {
            half2 h0 = __floats2half2_rn(sacc[2 * c][0], sacc[2 * c][1]);
            half2 h1v = __floats2half2_rn(sacc[2 * c][2], sacc[2 * c][3]);
            half2 h2 = __floats2half2_rn(sacc[2 * c + 1][0], sacc[2 * c + 1][1]);
            half2 h3 = __floats2half2_rn(sacc[2 * c + 1][2], sacc[2 * c + 1][3]);
            pa[c][0] = *(unsigned*)&h0;
            pa[c][1] = *(unsigned*)&h1v;
            pa[c][2] = *(unsigned*)&h2;
            pa[c][3] = *(unsigned*)&h3;
        }

        // ---- O += P @ V ----
#pragma unroll
        for (int jp = 0; jp < 4; jp++) {
#pragma unroll
            for (int c = 0; c < 4; c++) {
                unsigned bb[4];
                ldsm_x4_t(bb[0], bb[1], bb[2], bb[3],
                          &Vt[(c * 16 + vx_row) * LDK + jp * 16 + vx_col]);
                mma16816(oacc[2 * jp],     pa[c], bb);
                mma16816(oacc[2 * jp + 1], pa[c], bb + 2);
            }
        }
        buf = (buf == 2) ? 0 : buf + 1;
    }

    // ---- final row-sum reduction (deferred; sums are linear) ----
    l0 += __shfl_xor_sync(0xffffffffu, l0, 1);
    l0 += __shfl_xor_sync(0xffffffffu, l0, 2);
    l1 += __shfl_xor_sync(0xffffffffu, l1, 1);
    l1 += __shfl_xor_sync(0xffffffffu, l1, 2);

    // ---- normalize + write ----
    float inv0 = 1.0f / l0, inv1 = 1.0f / l1;
    int r0 = q0 + 16 * w + tq, r1 = r0 + 8;
#pragma unroll
    for (int j = 0; j < 8; j++) {
        int col = h * DH + j * 8 + 2 * tr;
        *(half2*)&outp[(size_t)r0 * CDIM + col] =
            __floats2half2_rn(oacc[j][0] * inv0, oacc[j][1] * inv0);
        *(half2*)&outp[(size_t)r1 * CDIM + col] =
            __floats2half2_rn(oacc[j][2] * inv1, oacc[j][3] * inv1);
    }
}

// ---------------- launch ----------------
extern "C" void kernel_launch(void* const* d_in, const int* in_sizes, int n_in,
                              void* d_out, int out_size) {
    const float* q        = (const float*)d_in[0];
    const float* k        = (const float*)d_in[1];
    const float* v        = (const float*)d_in[2];
    const float* ln_q_g   = (const float*)d_in[3];
    const float* ln_q_b   = (const float*)d_in[4];
    const float* ln_k_g   = (const float*)d_in[5];
    const float* ln_k_b   = (const float*)d_in[6];
    const float* ln_v_g   = (const float*)d_in[7];
    const float* ln_v_b   = (const float*)d_in[8];
    const float* Wq       = (const float*)d_in[9];
    const float* bq       = (const float*)d_in[10];
    const float* Wk       = (const float*)d_in[11];
    const float* bk       = (const float*)d_in[12];
    const float* Wv       = (const float*)d_in[13];
    const float* bv       = (const float*)d_in[14];
    const float* Wp       = (const float*)d_in[15];
    const float* bp       = (const float*)d_in[16];
    const float* ln_pre_g = (const float*)d_in[17];
    const float* ln_pre_b = (const float*)d_in[18];
    const float* W1       = (const float*)d_in[19];
    const float* b1       = (const float*)d_in[20];
    const float* W2       = (const float*)d_in[21];
    const float* b2       = (const float*)d_in[22];
    const float* ln_po_g  = (const float*)d_in[23];
    const float* ln_po_b  = (const float*)d_in[24];
    float* out = (float*)d_out;

    __half *qn, *kn, *vn, *qh, *kh, *vh, *at, *z0, *z1, *h1;
    __half *Wqh, *Wkh, *Wvh, *Wph, *W1h, *W2h;
    float *z2;
    cudaGetSymbolAddress((void**)&qn, g_qn);
    cudaGetSymbolAddress((void**)&kn, g_kn);
    cudaGetSymbolAddress((void**)&vn, g_vn);
    cudaGetSymbolAddress((void**)&qh, g_qh);
    cudaGetSymbolAddress((void**)&kh, g_kh);
    cudaGetSymbolAddress((void**)&vh, g_vh);
    cudaGetSymbolAddress((void**)&at, g_at);
    cudaGetSymbolAddress((void**)&z0, g_z0);
    cudaGetSymbolAddress((void**)&z1, g_z1);
    cudaGetSymbolAddress((void**)&h1, g_h1);
    cudaGetSymbolAddress((void**)&z2, g_z2);
    cudaGetSymbolAddress((void**)&Wqh, g_Wqh);
    cudaGetSymbolAddress((void**)&Wkh, g_Wkh);
    cudaGetSymbolAddress((void**)&Wvh, g_Wvh);
    cudaGetSymbolAddress((void**)&Wph, g_Wph);
    cudaGetSymbolAddress((void**)&W1h, g_W1h);
    cudaGetSymbolAddress((void**)&W2h, g_W2h);

    // 0) all weights -> fp16 (one launch)
    f2h_all<<<4096, 256>>>(Wq, Wk, Wv, Wp, W1, W2, Wqh, Wkh, Wvh, Wph, W1h, W2h);

    // 1) all three input LNs in one launch (range-batched)
    ln_in_all<<<768, 256>>>(q, k, v, ln_q_g, ln_q_b, ln_k_g, ln_k_b, ln_v_g, ln_v_b,
                            qn, kn, vn);

    // 2) QKV projections: packed 1-D grid, no empty blocks
    qkv_gemm<<<384, 256>>>(qn, kn, vn, Wqh, Wkh, Wvh, bq, bk, bv, qh, kh, vh);

    // 3) flash attention (R13 config: 16 warps, BKV=64, fp32 exp2)
    attn_h<<<dim3(NQ / BQ, HEADS), 512>>>(qh, kh, vh, at);

    // 4) output projection + pre-LN
    hgemm<<<dim3(CDIM / 128, NQ / 128), 256>>>(at, Wph, bp, nullptr, z0, nullptr, CDIM, CDIM, 0);
    ln_rows_h<<<NQ, 256>>>(z0, ln_pre_g, ln_pre_b, z1);

    // 5) MLP
    hgemm<<<dim3(FF / 128, NQ / 128), 256>>>(z1, W1h, b1, nullptr, h1, nullptr, FF, CDIM, 1);
    hgemm<<<dim3(CDIM / 128, NQ / 128), 256>>>(h1, W2h, b2, z1, nullptr, z2, CDIM, FF, 0);

    // 6) post-LN + transpose back to (C, N)
    ln_out_fused<<<NQ / 16, 256>>>(z2, ln_po_g, ln_po_b, out, NQ);
}

// round 16
// speedup vs baseline: 1.0530x; 1.0278x over previous
#include <cuda_runtime.h>
#include <cuda_fp16.h>
#include <math.h>

#define NQ     8192
#define NKV    2048
#define CDIM   512
#define HEADS  8
#define DH     64
#define FF     1024
#define LN_EPS 1e-5f

// ---------------- scratch (device globals) ----------------
__device__ __half g_qn[NQ * CDIM];
__device__ __half g_kn[NKV * CDIM];
__device__ __half g_vn[NKV * CDIM];
__device__ __half g_qh[NQ * CDIM];
__device__ __half g_kh[NKV * CDIM];
__device__ __half g_vh[NKV * CDIM];
__device__ __half g_at[NQ * CDIM];
__device__ __half g_z0[NQ * CDIM];
__device__ __half g_z1[NQ * CDIM];
__device__ __half g_h1[NQ * FF];
__device__ float  g_z2[NQ * CDIM];
__device__ __half g_Wqh[CDIM * CDIM];
__device__ __half g_Wkh[CDIM * CDIM];
__device__ __half g_Wvh[CDIM * CDIM];
__device__ __half g_Wph[CDIM * CDIM];
__device__ __half g_W1h[CDIM * FF];
__device__ __half g_W2h[FF * CDIM];

// ---------------- async copy helpers ----------------
__device__ __forceinline__ void cp16(void* sdst, const void* gsrc) {
    unsigned d = (unsigned)__cvta_generic_to_shared(sdst);
    asm volatile("cp.async.cg.shared.global [%0], [%1], 16;\n" :: "r"(d), "l"(gsrc));
}
__device__ __forceinline__ void cp_commit() {
    asm volatile("cp.async.commit_group;\n");
}
__device__ __forceinline__ void cp_wait1() {
    asm volatile("cp.async.wait_group 1;\n");
}
__device__ __forceinline__ void cp_wait0() {
    asm volatile("cp.async.wait_group 0;\n");
}

// ---------------- ldmatrix helpers ----------------
__device__ __forceinline__ void ldsm_x4(unsigned& r0, unsigned& r1, unsigned& r2,
                                        unsigned& r3, const __half* p) {
    unsigned a = (unsigned)__cvta_generic_to_shared(p);
    asm volatile("ldmatrix.sync.aligned.m8n8.x4.shared.b16 {%0,%1,%2,%3}, [%4];\n"
                 : "=r"(r0), "=r"(r1), "=r"(r2), "=r"(r3) : "r"(a));
}
__device__ __forceinline__ void ldsm_x4_t(unsigned& r0, unsigned& r1, unsigned& r2,
                                          unsigned& r3, const __half* p) {
    unsigned a = (unsigned)__cvta_generic_to_shared(p);
    asm volatile("ldmatrix.sync.aligned.m8n8.x4.trans.shared.b16 {%0,%1,%2,%3}, [%4];\n"
                 : "=r"(r0), "=r"(r1), "=r"(r2), "=r"(r3) : "r"(a));
}

// ---------------- mma.sync helper ----------------
__device__ __forceinline__ void mma16816(float* c, const unsigned* a, const unsigned* b) {
    asm volatile(
        "mma.sync.aligned.m16n8k16.row.col.f32.f16.f16.f32 "
        "{%0,%1,%2,%3}, {%4,%5,%6,%7}, {%8,%9}, {%0,%1,%2,%3};"
        : "+f"(c[0]), "+f"(c[1]), "+f"(c[2]), "+f"(c[3])
        : "r"(a[0]), "r"(a[1]), "r"(a[2]), "r"(a[3]), "r"(b[0]), "r"(b[1]));
}

// ---------------- all weight converts in one launch ----------------
__global__ void f2h_all(const float* Wq, const float* Wk, const float* Wv,
                        const float* Wp, const float* W1, const float* W2,
                        __half* Wqh, __half* Wkh, __half* Wvh,
                        __half* Wph, __half* W1h, __half* W2h) {
    int i = blockIdx.x * 256 + threadIdx.x;   // pair index
    const float* s; __half* d; int o;
    if      (i <  131072) { s = Wq; d = Wqh; o = i; }
    else if (i <  262144) { s = Wk; d = Wkh; o = i - 131072; }
    else if (i <  393216) { s = Wv; d = Wvh; o = i - 262144; }
    else if (i <  524288) { s = Wp; d = Wph; o = i - 393216; }
    else if (i <  786432) { s = W1; d = W1h; o = i - 524288; }
    else                  { s = W2; d = W2h; o = i - 786432; }
    float2 v = ((const float2*)s)[o];
    ((half2*)d)[o] = __floats2half2_rn(v.x, v.y);
}

// ---------------- batched channel-major LN: q/k/v in one launch ----------------
#define LDT 17
__global__ __launch_bounds__(256) void ln_in_all(
        const float* __restrict__ xq, const float* __restrict__ xk, const float* __restrict__ xv,
        const float* __restrict__ gq, const float* __restrict__ bq_,
        const float* __restrict__ gk, const float* __restrict__ bk_,
        const float* __restrict__ gv, const float* __restrict__ bv_,
        __half* __restrict__ yq, __half* __restrict__ yk, __half* __restrict__ yv) {
    __shared__ float t[512 * LDT];
    __shared__ float smu[16], srs[16];
    int bid = blockIdx.x, tid = threadIdx.x;
    const float *x, *g, *b; __half* y; int N, n0;
    if (bid < 512)      { x = xq; g = gq; b = bq_; y = yq; N = NQ;  n0 = bid * 16; }
    else if (bid < 640) { x = xk; g = gk; b = bk_; y = yk; N = NKV; n0 = (bid - 512) * 16; }
    else                { x = xv; g = gv; b = bv_; y = yv; N = NKV; n0 = (bid - 640) * 16; }
#pragma unroll
    for (int p = 0; p < 32; p++) {
        int ch = p * 16 + (tid >> 4), tok = tid & 15;
        t[ch * LDT + tok] = x[(size_t)ch * N + n0 + tok];
    }
    __syncthreads();
    int w = tid >> 5, lane = tid & 31;
    int tok = 2 * w + (lane >> 4), lid = lane & 15;
    float s = 0.f, s2 = 0.f;
#pragma unroll
    for (int i = 0; i < 32; i++) {
        float v = t[(lid + i * 16) * LDT + tok];
        s += v; s2 += v * v;
    }
#pragma unroll
    for (int o = 1; o < 16; o <<= 1) {
        s  += __shfl_xor_sync(0xffffffffu, s,  o);
        s2 += __shfl_xor_sync(0xffffffffu, s2, o);
    }
    if (lid == 0) {
        float m = s * (1.0f / CDIM);
        smu[tok] = m;
        srs[tok] = rsqrtf(s2 * (1.0f / CDIM) - m * m + LN_EPS);
    }
    __syncthreads();
#pragma unroll
    for (int p = 0; p < 16; p++) {
        int flat = p * 256 + tid;
        int tk = flat >> 8, ch = (flat & 255) * 2;
        float mu = smu[tk], rs = srs[tk];
        float v0 = (t[ch * LDT + tk] - mu) * rs * g[ch] + b[ch];
        float v1 = (t[(ch + 1) * LDT + tk] - mu) * rs * g[ch + 1] + b[ch + 1];
        ((half2*)(y + (size_t)(n0 + tk) * CDIM))[ch >> 1] = __floats2half2_rn(v0, v1);
    }
}

// ---------------- fused row LN + transpose out ----------------
#define LDZ 513
__global__ __launch_bounds__(256) void ln_out_fused(
        const float* __restrict__ z, const float* __restrict__ g,
        const float* __restrict__ b, float* __restrict__ out, int N) {
    __shared__ float t[16 * LDZ];
    __shared__ float smu[16], srs[16];
    int n0 = blockIdx.x * 16, tid = threadIdx.x;
#pragma unroll
    for (int p = 0; p < 8; p++) {
        int f4 = p * 256 + tid;
        int tok = f4 >> 7, ch = (f4 & 127) * 4;
        float4 v = ((const float4*)(z + (size_t)(n0 + tok) * CDIM))[f4 & 127];
        t[tok * LDZ + ch] = v.x; t[tok * LDZ + ch + 1] = v.y;
        t[tok * LDZ + ch + 2] = v.z; t[tok * LDZ + ch + 3] = v.w;
    }
    __syncthreads();
    int w = tid >> 5, lane = tid & 31;
    int tok = 2 * w + (lane >> 4), lid = lane & 15;
    float s = 0.f, s2 = 0.f;
#pragma unroll
    for (int i = 0; i < 32; i++) {
        float v = t[tok * LDZ + lid + i * 16];
        s += v; s2 += v * v;
    }
#pragma unroll
    for (int o = 1; o < 16; o <<= 1) {
        s  += __shfl_xor_sync(0xffffffffu, s,  o);
        s2 += __shfl_xor_sync(0xffffffffu, s2, o);
    }
    if (lid == 0) {
        float m = s * (1.0f / CDIM);
        smu[tok] = m;
        srs[tok] = rsqrtf(s2 * (1.0f / CDIM) - m * m + LN_EPS);
    }
    __syncthreads();
#pragma unroll
    for (int p = 0; p < 32; p++) {
        int flat = p * 256 + tid;
        int ch = flat >> 4, tk = flat & 15;
        out[(size_t)ch * N + n0 + tk] =
            (t[tk * LDZ + ch] - smu[tk]) * srs[tk] * g[ch] + b[ch];
    }
}

// ---------------- row LN fp16 -> fp16: warp-per-row, no smem, no syncthreads ----------------
__global__ __launch_bounds__(256) void ln_rows_h(
        const __half* __restrict__ x, const float* __restrict__ g,
        const float* __restrict__ b, __half* __restrict__ y) {
    int w = threadIdx.x >> 5, lane = threadIdx.x & 31;
    int row = blockIdx.x * 8 + w;
    const uint4* xr4 = (const uint4*)(x + (size_t)row * CDIM);
    uint4 hv0 = xr4[lane];
    uint4 hv1 = xr4[lane + 32];
    float v[16];
    {
        const half2* p0 = (const half2*)&hv0;
        const half2* p1 = (const half2*)&hv1;
#pragma unroll
        for (int i = 0; i < 4; i++) {
            float2 f = __half22float2(p0[i]);
            v[2 * i] = f.x; v[2 * i + 1] = f.y;
        }
#pragma unroll
        for (int i = 0; i < 4; i++) {
            float2 f = __half22float2(p1[i]);
            v[8 + 2 * i] = f.x; v[8 + 2 * i + 1] = f.y;
        }
    }
    float s = 0.f, s2 = 0.f;
#pragma unroll
    for (int i = 0; i < 16; i++) { s += v[i]; s2 += v[i] * v[i]; }
#pragma unroll
    for (int o = 16; o > 0; o >>= 1) {
        s  += __shfl_xor_sync(0xffffffffu, s,  o);
        s2 += __shfl_xor_sync(0xffffffffu, s2, o);
    }
    float m = s * (1.0f / CDIM);
    float rstd = rsqrtf(s2 * (1.0f / CDIM) - m * m + LN_EPS);
    uint4* yr4 = (uint4*)(y + (size_t)row * CDIM);
#pragma unroll
    for (int c = 0; c < 2; c++) {
        int f4base = (lane + c * 32) * 2;      // float4 index into g/b
        float4 g0 = ((const float4*)g)[f4base];
        float4 g1 = ((const float4*)g)[f4base + 1];
        float4 b0 = ((const float4*)b)[f4base];
        float4 b1 = ((const float4*)b)[f4base + 1];
        const float* vv = v + c * 8;
        uint4 outv;
        half2* oh = (half2*)&outv;
        oh[0] = __floats2half2_rn((vv[0] - m) * rstd * g0.x + b0.x,
                                  (vv[1] - m) * rstd * g0.y + b0.y);
        oh[1] = __floats2half2_rn((vv[2] - m) * rstd * g0.z + b0.z,
                                  (vv[3] - m) * rstd * g0.w + b0.w);
        oh[2] = __floats2half2_rn((vv[4] - m) * rstd * g1.x + b1.x,
                                  (vv[5] - m) * rstd * g1.y + b1.y);
        oh[3] = __floats2half2_rn((vv[6] - m) * rstd * g1.z + b1.z,
                                  (vv[7] - m) * rstd * g1.w + b1.w);
        yr4[lane + c * 32] = outv;
    }
}

// ---------------- GEMM (R13 exact): raw mma, 128x128 tile, 8 warps x 32x64, BK=32,
//                  cp.async 3-stage, 1 sync/iter, direct-register epilogue ----------------
#define LDA_S 40
#define LDB_S 136
struct SmemGemm {
    __half As[3][128 * LDA_S];
    __half Bs[3][32 * LDB_S];
};

__device__ __forceinline__ void gemm_body(
        SmemGemm* sm,
        const __half* __restrict__ A, const __half* __restrict__ B,
        const float* __restrict__ bias, const __half* __restrict__ res,
        __half* __restrict__ Ch, float* __restrict__ Cf,
        int N, int K, int doGelu, int m0, int n0) {
    int tid = threadIdx.x;
    int lane = tid & 31;
    int w = tid >> 5;
    int wm = w >> 1, wn = w & 1;     // warp tile: rows 32*wm, cols 64*wn
    int tq = lane >> 2, tr = lane & 3;

    float acc[2][8][4];
#pragma unroll
    for (int i = 0; i < 2; i++)
#pragma unroll
        for (int j = 0; j < 8; j++)
#pragma unroll
            for (int r = 0; r < 4; r++) acc[i][j][r] = 0.f;

    int ar = tid >> 1, ac = (tid & 1) * 16;
    int br = tid >> 3, bc = (tid & 7) * 16;
    const __half* apb = A + (size_t)(m0 + ar) * K + ac;
    const __half* bpb = B + (size_t)br * N + n0 + bc;

    // prefetch tiles 0 and 1
#pragma unroll
    for (int p = 0; p < 2; p++) {
        int k0 = p * 32;
        cp16(&sm->As[p][ar * LDA_S + ac],     apb + k0);
        cp16(&sm->As[p][ar * LDA_S + ac + 8], apb + k0 + 8);
        cp16(&sm->Bs[p][br * LDB_S + bc],     bpb + (size_t)k0 * N);
        cp16(&sm->Bs[p][br * LDB_S + bc + 8], bpb + (size_t)k0 * N + 8);
        cp_commit();
    }

    const int ax_row = (lane & 15);
    const int ax_col = ((lane & 16) >> 1);
    const int bx_row = (lane & 15);
    const int bx_col = ((lane & 16) >> 1);

    int nT = K >> 5;
    int buf = 0;
    for (int t = 0; t < nT; t++) {
        if (t == nT - 1) cp_wait0(); else cp_wait1();
        __syncthreads();
        if (t + 2 < nT) {
            int k0 = (t + 2) * 32;
            int nb = (buf + 2 >= 3) ? buf - 1 : buf + 2;
            cp16(&sm->As[nb][ar * LDA_S + ac],     apb + k0);
            cp16(&sm->As[nb][ar * LDA_S + ac + 8], apb + k0 + 8);
            cp16(&sm->Bs[nb][br * LDB_S + bc],     bpb + (size_t)k0 * N);
            cp16(&sm->Bs[nb][br * LDB_S + bc + 8], bpb + (size_t)k0 * N + 8);
            cp_commit();
        }
        const __half* Asb = sm->As[buf];
        const __half* Bsb = sm->Bs[buf];
#pragma unroll
        for (int ks = 0; ks < 2; ks++) {
            unsigned af[2][4];
#pragma unroll
            for (int mi = 0; mi < 2; mi++)
                ldsm_x4(af[mi][0], af[mi][1], af[mi][2], af[mi][3],
                        &Asb[(32 * wm + 16 * mi + ax_row) * LDA_S + 16 * ks + ax_col]);
#pragma unroll
            for (int np = 0; np < 4; np++) {
                unsigned bb[4];
                ldsm_x4_t(bb[0], bb[1], bb[2], bb[3],
                          &Bsb[(16 * ks + bx_row) * LDB_S + 64 * wn + 16 * np + bx_col]);
#pragma unroll
                for (int mi = 0; mi < 2; mi++) {
                    mma16816(acc[mi][2 * np],     af[mi], bb);
                    mma16816(acc[mi][2 * np + 1], af[mi], bb + 2);
                }
            }
        }
        buf = (buf == 2) ? 0 : buf + 1;
    }

    // direct-register epilogue: rows tq / tq+8, cols 2*tr / 2*tr+1
#pragma unroll
    for (int mi = 0; mi < 2; mi++) {
        int r0 = m0 + 32 * wm + 16 * mi + tq;
        int r1 = r0 + 8;
#pragma unroll
        for (int nj = 0; nj < 8; nj++) {
            int col = n0 + 64 * wn + 8 * nj + 2 * tr;
            float b0 = bias[col], b1 = bias[col + 1];
            float v0 = acc[mi][nj][0] + b0;
            float v1 = acc[mi][nj][1] + b1;
            float v2 = acc[mi][nj][2] + b0;
            float v3 = acc[mi][nj][3] + b1;
            if (doGelu) {
                v0 = 0.5f * v0 * (1.0f + erff(v0 * 0.70710678118654752f));
                v1 = 0.5f * v1 * (1.0f + erff(v1 * 0.70710678118654752f));
                v2 = 0.5f * v2 * (1.0f + erff(v2 * 0.70710678118654752f));
                v3 = 0.5f * v3 * (1.0f + erff(v3 * 0.70710678118654752f));
            }
            if (res) {
                half2 r0v = *(const half2*)&res[(size_t)r0 * N + col];
                half2 r1v = *(const half2*)&res[(size_t)r1 * N + col];
                v0 += __half2float(r0v.x); v1 += __half2float(r0v.y);
                v2 += __half2float(r1v.x); v3 += __half2float(r1v.y);
            }
            if (Ch) {
                *(half2*)&Ch[(size_t)r0 * N + col] = __floats2half2_rn(v0, v1);
                *(half2*)&Ch[(size_t)r1 * N + col] = __floats2half2_rn(v2, v3);
            }
            if (Cf) {
                *(float2*)&Cf[(size_t)r0 * N + col] = make_float2(v0, v1);
                *(float2*)&Cf[(size_t)r1 * N + col] = make_float2(v2, v3);
            }
        }
    }
}

// generic GEMM (256 threads, 8 warps, 2 blocks/SM)
__global__ __launch_bounds__(256, 2) void hgemm(
        const __half* __restrict__ A, const __half* __restrict__ B,
        const float* __restrict__ bias, const __half* __restrict__ res,
        __half* __restrict__ Ch, float* __restrict__ Cf,
        int N, int K, int doGelu) {
    __shared__ SmemGemm sm;
    gemm_body(&sm, A, B, bias, res, Ch, Cf, N, K, doGelu,
              blockIdx.y * 128, blockIdx.x * 128);
}

// packed 1-D QKV projection: 256 Q-blocks + 64 K-blocks + 64 V-blocks = 384
__global__ __launch_bounds__(256, 2) void qkv_gemm(
        const __half* qn, const __half* kn, const __half* vn,
        const __half* Wq, const __half* Wk, const __half* Wv,
        const float* bq, const float* bk, const float* bv,
        __half* qh, __half* kh, __half* vh) {
    int bid = blockIdx.x;
    const __half *A, *B; const float* bias; __half* C; int sub;
    if (bid < 256)      { A = qn; B = Wq; bias = bq; C = qh; sub = bid; }
    else if (bid < 320) { A = kn; B = Wk; bias = bk; C = kh; sub = bid - 256; }
    else                { A = vn; B = Wv; bias = bv; C = vh; sub = bid - 320; }
    int m0 = (sub >> 2) * 128;
    int n0 = (sub & 3) * 128;
    __shared__ SmemGemm sm;
    gemm_body(&sm, A, B, bias, nullptr, C, nullptr, CDIM, CDIM, 0, m0, n0);
}

// ---------------- flash attention (R13 exact): 256 q x 1 head / block, 16 warps, BKV=64,
//                  3-stage KV ring, no-max exp2 softmax (fp32), 1 sync/iter ----------------
#define LDK 72
#define BQ  256
__global__ __launch_bounds__(512) void attn_h(
        const __half* __restrict__ qh, const __half* __restrict__ kh,
        const __half* __restrict__ vh, __half* __restrict__ outp) {
    __shared__ __half Qs[BQ * LDK];           // 36.9 KB, persistent
    __shared__ __half SM[3][2 * 64 * LDK];    // K then V per stage, 55.3 KB

    const int tid = threadIdx.x;
    const int lane = tid & 31;
    const int w = tid >> 5;            // 0..15, owns q rows 16w..16w+15
    const int h = blockIdx.y;
    const int q0 = blockIdx.x * BQ;
    const int tq = lane >> 2;
    const int tr = lane & 3;

    // KV loader mapping: 512 threads, 64x64 tile = 512 x16B chunks
    const int lrow = tid >> 3;              // 0..63
    const int lcol = (tid & 7) * 8;         // 0..56 (halfs)

    // loop-carried gmem prefetch pointers
    const __half* kgp = kh + (size_t)lrow * CDIM + h * DH + lcol;
    const __half* vgp = vh + (size_t)lrow * CDIM + h * DH + lcol;

    // prefetch KV tiles 0 and 1
#pragma unroll
    for (int p = 0; p < 2; p++) {
        cp16(&SM[p][lrow * LDK + lcol], kgp + (size_t)p * 64 * CDIM);
        cp16(&SM[p][64 * LDK + lrow * LDK + lcol], vgp + (size_t)p * 64 * CDIM);
        cp_commit();
    }
    kgp += (size_t)128 * CDIM;   // next prefetch target = tile 2
    vgp += (size_t)128 * CDIM;

    // ---- stage Q (256 x 64), scale folds 1/8 AND log2(e) for exp2 softmax ----
    {
        int r = tid >> 1, cb = (tid & 1) * 32;
        const __half* src = qh + (size_t)(q0 + r) * CDIM + h * DH + cb;
        half2 scale = __half2half2(__float2half(0.125f * 1.4426950408889634f));
        half2* d = (half2*)&Qs[r * LDK + cb];
#pragma unroll
        for (int i = 0; i < 16; i++)
            d[i] = __hmul2(((const half2*)src)[i], scale);
    }
    __syncthreads();   // Qs visible to all warps

    // Q fragments (registers, persistent)
    unsigned qa[4][4];
    {
        int r0 = 16 * w + tq, r1 = r0 + 8;
#pragma unroll
        for (int c = 0; c < 4; c++) {
            int d0 = c * 16 + 2 * tr;
            qa[c][0] = *(const unsigned*)&Qs[r0 * LDK + d0];
            qa[c][1] = *(const unsigned*)&Qs[r1 * LDK + d0];
            qa[c][2] = *(const unsigned*)&Qs[r0 * LDK + d0 + 8];
            qa[c][3] = *(const unsigned*)&Qs[r1 * LDK + d0 + 8];
        }
    }

    // x4 ldmatrix index helpers
    const int kx_row = (lane & 7) + ((lane & 16) >> 1);
    const int kx_col = (lane & 8);
    const int vx_row = (lane & 15);
    const int vx_col = ((lane & 16) >> 1);

    float l0 = 0.f, l1 = 0.f;     // per-lane partial sums (reduced at end)
    float oacc[8][4];
#pragma unroll
    for (int j = 0; j < 8; j++)
#pragma unroll
        for (int r = 0; r < 4; r++) oacc[j][r] = 0.f;

    const int NT = NKV / 64;   // 32
    int buf = 0;
    for (int it = 0; it < NT; it++) {
        if (it == NT - 1) cp_wait0(); else cp_wait1();
        __syncthreads();   // tile `it` ready for all; all warps done with tile it-1

        // prefetch tile it+2 into the ring slot freed by tile it-1
        if (it + 2 < NT) {
            int nb = (buf + 2 >= 3) ? buf - 1 : buf + 2;
            cp16(&SM[nb][lrow * LDK + lcol], kgp);
            cp16(&SM[nb][64 * LDK + lrow * LDK + lcol], vgp);
            cp_commit();
            kgp += (size_t)64 * CDIM;
            vgp += (size_t)64 * CDIM;
        }

        const __half* Kt = &SM[buf][0];
        const __half* Vt = &SM[buf][64 * LDK];

        // ---- S' = (Q*log2e/8) @ K^T ----
        float sacc[8][4];
#pragma unroll
        for (int j = 0; j < 8; j++)
#pragma unroll
            for (int r = 0; r < 4; r++) sacc[j][r] = 0.f;
#pragma unroll
        for (int jp = 0; jp < 4; jp++) {
#pragma unroll
            for (int c = 0; c < 4; c++) {
                unsigned bb[4];
                ldsm_x4(bb[0], bb[1], bb[2], bb[3],
                        &Kt[(jp * 16 + kx_row) * LDK + c * 16 + kx_col]);
                mma16816(sacc[2 * jp],     qa[c], bb);
                mma16816(sacc[2 * jp + 1], qa[c], bb + 2);
            }
        }

        // ---- softmax: fp32 exp2 (log2e folded into Q scale), no max subtraction ----
#pragma unroll
        for (int j = 0; j < 8; j++) {
            sacc[j][0] = exp2f(sacc[j][0]);
            sacc[j][1] = exp2f(sacc[j][1]);
            sacc[j][2] = exp2f(sacc[j][2]);
            sacc[j][3] = exp2f(sacc[j][3]);
            l0 += sacc[j][0] + sacc[j][1];
            l1 += sacc[j][2] + sacc[j][3];
        }

        // ---- P fragments from S accumulators (register-only) ----
        unsigned pa[4][4];
#pragma unroll
        for (int c = 0; c < 4; c++) {
            half2 h0 = __floats2half2_rn(sacc[2 * c][0], sacc[2 * c][1]);
            half2 h1v = __floats2half2_rn(sacc[2 * c][2], sacc[2 * c][3]);
            half2 h2 = __floats2half2_rn(sacc[2 * c + 1][0], sacc[2 * c + 1][1]);
            half2 h3 = __floats2half2_rn(sacc[2 * c + 1][2], sacc[2 * c + 1][3]);
            pa[c][0] = *(unsigned*)&h0;
            pa[c][1] = *(unsigned*)&h1v;
            pa[c][2] = *(unsigned*)&h2;
            pa[c][3] = *(unsigned*)&h3;
        }

        // ---- O += P @ V ----
#pragma unroll
        for (int jp = 0; jp < 4; jp++) {
#pragma unroll
            for (int c = 0; c < 4; c++) {
                unsigned bb[4];
                ldsm_x4_t(bb[0], bb[1], bb[2], bb[3],
                          &Vt[(c * 16 + vx_row) * LDK + jp * 16 + vx_col]);
                mma16816(oacc[2 * jp],     pa[c], bb);
                mma16816(oacc[2 * jp + 1], pa[c], bb + 2);
            }
        }
        buf = (buf == 2) ? 0 : buf + 1;
    }

    // ---- final row-sum reduction (deferred; sums are linear) ----
    l0 += __shfl_xor_sync(0xffffffffu, l0, 1);
    l0 += __shfl_xor_sync(0xffffffffu, l0, 2);
    l1 += __shfl_xor_sync(0xffffffffu, l1, 1);
    l1 += __shfl_xor_sync(0xffffffffu, l1, 2);

    // ---- normalize + write ----
    float inv0 = 1.0f / l0, inv1 = 1.0f / l1;
    int r0 = q0 + 16 * w + tq, r1 = r0 + 8;
#pragma unroll
    for (int j = 0; j < 8; j++) {
        int col = h * DH + j * 8 + 2 * tr;
        *(half2*)&outp[(size_t)r0 * CDIM + col] =
            __floats2half2_rn(oacc[j][0] * inv0, oacc[j][1] * inv0);
        *(half2*)&outp[(size_t)r1 * CDIM + col] =
            __floats2half2_rn(oacc[j][2] * inv1, oacc[j][3] * inv1);
    }
}

// ---------------- launch ----------------
extern "C" void kernel_launch(void* const* d_in, const int* in_sizes, int n_in,
                              void* d_out, int out_size) {
    const float* q        = (const float*)d_in[0];
    const float* k        = (const float*)d_in[1];
    const float* v        = (const float*)d_in[2];
    const float* ln_q_g   = (const float*)d_in[3];
    const float* ln_q_b   = (const float*)d_in[4];
    const float* ln_k_g   = (const float*)d_in[5];
    const float* ln_k_b   = (const float*)d_in[6];
    const float* ln_v_g   = (const float*)d_in[7];
    const float* ln_v_b   = (const float*)d_in[8];
    const float* Wq       = (const float*)d_in[9];
    const float* bq       = (const float*)d_in[10];
    const float* Wk       = (const float*)d_in[11];
    const float* bk       = (const float*)d_in[12];
    const float* Wv       = (const float*)d_in[13];
    const float* bv       = (const float*)d_in[14];
    const float* Wp       = (const float*)d_in[15];
    const float* bp       = (const float*)d_in[16];
    const float* ln_pre_g = (const float*)d_in[17];
    const float* ln_pre_b = (const float*)d_in[18];
    const float* W1       = (const float*)d_in[19];
    const float* b1       = (const float*)d_in[20];
    const float* W2       = (const float*)d_in[21];
    const float* b2       = (const float*)d_in[22];
    const float* ln_po_g  = (const float*)d_in[23];
    const float* ln_po_b  = (const float*)d_in[24];
    float* out = (float*)d_out;

    __half *qn, *kn, *vn, *qh, *kh, *vh, *at, *z0, *z1, *h1;
    __half *Wqh, *Wkh, *Wvh, *Wph, *W1h, *W2h;
    float *z2;
    cudaGetSymbolAddress((void**)&qn, g_qn);
    cudaGetSymbolAddress((void**)&kn, g_kn);
    cudaGetSymbolAddress((void**)&vn, g_vn);
    cudaGetSymbolAddress((void**)&qh, g_qh);
    cudaGetSymbolAddress((void**)&kh, g_kh);
    cudaGetSymbolAddress((void**)&vh, g_vh);
    cudaGetSymbolAddress((void**)&at, g_at);
    cudaGetSymbolAddress((void**)&z0, g_z0);
    cudaGetSymbolAddress((void**)&z1, g_z1);
    cudaGetSymbolAddress((void**)&h1, g_h1);
    cudaGetSymbolAddress((void**)&z2, g_z2);
    cudaGetSymbolAddress((void**)&Wqh, g_Wqh);
    cudaGetSymbolAddress((void**)&Wkh, g_Wkh);
    cudaGetSymbolAddress((void**)&Wvh, g_Wvh);
    cudaGetSymbolAddress((void**)&Wph, g_Wph);
    cudaGetSymbolAddress((void**)&W1h, g_W1h);
    cudaGetSymbolAddress((void**)&W2h, g_W2h);

    // 0) all weights -> fp16 (one launch)
    f2h_all<<<4096, 256>>>(Wq, Wk, Wv, Wp, W1, W2, Wqh, Wkh, Wvh, Wph, W1h, W2h);

    // 1) all three input LNs in one launch (range-batched)
    ln_in_all<<<768, 256>>>(q, k, v, ln_q_g, ln_q_b, ln_k_g, ln_k_b, ln_v_g, ln_v_b,
                            qn, kn, vn);

    // 2) QKV projections: packed 1-D grid, no empty blocks
    qkv_gemm<<<384, 256>>>(qn, kn, vn, Wqh, Wkh, Wvh, bq, bk, bv, qh, kh, vh);

    // 3) flash attention (R13 config: 16 warps, BKV=64, fp32 exp2)
    attn_h<<<dim3(NQ / BQ, HEADS), 512>>>(qh, kh, vh, at);

    // 4) output projection + pre-LN (warp-per-row LN)
    hgemm<<<dim3(CDIM / 128, NQ / 128), 256>>>(at, Wph, bp, nullptr, z0, nullptr, CDIM, CDIM, 0);
    ln_rows_h<<<NQ / 8, 256>>>(z0, ln_pre_g, ln_pre_b, z1);

    // 5) MLP
    hgemm<<<dim3(FF / 128, NQ / 128), 256>>>(z1, W1h, b1, nullptr, h1, nullptr, FF, CDIM, 1);
    hgemm<<<dim3(CDIM / 128, NQ / 128), 256>>>(h1, W2h, b2, z1, nullptr, z2, CDIM, FF, 0);

    // 6) post-LN + transpose back to (C, N)
    ln_out_fused<<<NQ / 16, 256>>>(z2, ln_po_g, ln_po_b, out, NQ);
}